// round 5
// baseline (speedup 1.0000x reference)
#include <cuda_runtime.h>
#include <cstdint>

// HierarchicalLoss on GB300 sm_103a — fully fused single kernel.
//
// loss = mean(level_w[n] * (softplus(x) - x*t))
//      + 0.5/(B*N) * sum_{b,e} relu(sigmoid(x[b,dst_e]) - sigmoid(x[b,src_e]))
//
// 128 CTAs x 32 rows, 512 threads, 1 CTA/SM.
// Phase 1: stream outputs/targets with a manual double-buffered load pipeline,
//          compute weighted BCE, quantize sigmoid to u8, store ROW-PACKED in
//          smem probs[col][row] (col stride 40B -> conflict-free packed stores).
// Phase 2: SIMD u8 edge consistency: __vsubus4 (per-byte relu) + __dp4a,
//          exact integer accumulation, /255 at the end.
// Finalize: per-CTA partials overwritten into __device__ slots (no zeroing
//          needed -> graph-replay safe); last CTA (monotonic atomic counter,
//          (old+1) % 128 == 0) reduces 128 partials and writes d_out.

#define B_DIM 4096
#define N_DIM 4096
#define E_DIM 16384
#define ROWS_PER_CTA 32
#define NUM_CTAS (B_DIM / ROWS_PER_CTA)      // 128
#define THREADS 512
#define CSW 10                                // 40 B column stride (32 rows + 8 pad)
#define PROBS_BYTES (N_DIM * CSW * 4)         // 163840
#define SMEM_BYTES (PROBS_BYTES + E_DIM * 4)  // 229376

__device__ double             g_part_bce[NUM_CTAS];
__device__ unsigned long long g_part_cons[NUM_CTAS];
__device__ unsigned int       g_done;   // monotonically increasing; 2^32 is a multiple of 128

__device__ __forceinline__ void hl_load(const float* __restrict__ o,
                                        const float* __restrict__ t,
                                        size_t b0, float4* X, float4* T) {
#pragma unroll
    for (int rr = 0; rr < 4; ++rr) {
        X[rr] = *reinterpret_cast<const float4*>(o + b0 + (size_t)rr * N_DIM);
        T[rr] = *reinterpret_cast<const float4*>(t + b0 + (size_t)rr * N_DIM);
    }
}

__device__ __forceinline__ float hl_comp(const float4* X, const float4* T,
                                         float4 w4, unsigned* __restrict__ probs,
                                         int c0, int g) {
    unsigned pk0 = 0, pk1 = 0, pk2 = 0, pk3 = 0;
    float acc = 0.f;
#pragma unroll
    for (int rr = 0; rr < 4; ++rr) {
        {   float e = __expf(-X[rr].x); float u = 1.f + e; float lp = __logf(u);
            acc = fmaf(w4.x, fmaf(X[rr].x, 1.f - T[rr].x, lp), acc);
            pk0 |= __float2uint_rn(__fdividef(255.f, u)) << (8 * rr); }
        {   float e = __expf(-X[rr].y); float u = 1.f + e; float lp = __logf(u);
            acc = fmaf(w4.y, fmaf(X[rr].y, 1.f - T[rr].y, lp), acc);
            pk1 |= __float2uint_rn(__fdividef(255.f, u)) << (8 * rr); }
        {   float e = __expf(-X[rr].z); float u = 1.f + e; float lp = __logf(u);
            acc = fmaf(w4.z, fmaf(X[rr].z, 1.f - T[rr].z, lp), acc);
            pk2 |= __float2uint_rn(__fdividef(255.f, u)) << (8 * rr); }
        {   float e = __expf(-X[rr].w); float u = 1.f + e; float lp = __logf(u);
            acc = fmaf(w4.w, fmaf(X[rr].w, 1.f - T[rr].w, lp), acc);
            pk3 |= __float2uint_rn(__fdividef(255.f, u)) << (8 * rr); }
    }
    // word index (c0+j)*10 + g -> banks (8*(cb&3) + 10j + g) mod 32, conflict-free
    const int wb = c0 * CSW + g;
    probs[wb]           = pk0;
    probs[wb + CSW]     = pk1;
    probs[wb + 2 * CSW] = pk2;
    probs[wb + 3 * CSW] = pk3;
    return acc;
}

__global__ __launch_bounds__(THREADS, 1)
void hl_fused_kernel(const float* __restrict__ outputs,
                     const float* __restrict__ targets,
                     const float* __restrict__ level_w,
                     const int* __restrict__ edge_src,
                     const int* __restrict__ edge_dst,
                     float* __restrict__ out) {
    extern __shared__ unsigned char smem[];
    unsigned* probs_w = reinterpret_cast<unsigned*>(smem);
    unsigned* edges_w = reinterpret_cast<unsigned*>(smem + PROBS_BYTES);
    __shared__ double   s_red_b[16];
    __shared__ double   s_red_c[16];
    __shared__ unsigned s_last;

    const int tid = threadIdx.x;

    // ---- Stage edges packed as (dst | src<<16) ----
    for (int e = tid; e < E_DIM; e += THREADS) {
        edges_w[e] = (unsigned)edge_dst[e] | ((unsigned)edge_src[e] << 16);
    }

    // ---- Phase 1: BCE + quantized sigmoid, double-buffered load pipeline ----
    const int g  = tid & 7;                       // row-group (4 rows)
    const int cb = tid >> 3;                      // 0..63 column-block
    const int rbase = blockIdx.x * ROWS_PER_CTA + 4 * g;
    const size_t cbase = (size_t)rbase * N_DIM + 4 * cb;
    const int ccol = 4 * cb;

    float bce_acc = 0.f;
    float4 xa[4], ta[4], xb[4], tb[4];

    hl_load(outputs, targets, cbase, xa, ta);      // prologue: iter 0

#pragma unroll 1
    for (int ii = 0; ii < 8; ++ii) {
        const int i0 = 2 * ii, i1 = 2 * ii + 1;
        // prefetch iter i1 while computing i0
        hl_load(outputs, targets, cbase + 256 * i1, xb, tb);
        {
            const float4 w4 = *reinterpret_cast<const float4*>(level_w + ccol + 256 * i0);
            bce_acc += hl_comp(xa, ta, w4, probs_w, ccol + 256 * i0, g);
        }
        // prefetch iter i1+1 while computing i1
        if (ii < 7) hl_load(outputs, targets, cbase + 256 * (i1 + 1), xa, ta);
        {
            const float4 w4 = *reinterpret_cast<const float4*>(level_w + ccol + 256 * i1);
            bce_acc += hl_comp(xb, tb, w4, probs_w, ccol + 256 * i1, g);
        }
    }

    __syncthreads();

    // ---- Phase 2: edge consistency (SIMD u8) ----
    const int warp = tid >> 5;
    const int lane = tid & 31;
    const int eg = lane >> 3;   // edge within quad
    const int ch = lane & 7;    // u32 chunk (4 rows)

    unsigned cons = 0;
    const int ebase = warp * (E_DIM / 16);    // 1024 edges per warp

#pragma unroll 8
    for (int it = 0; it < E_DIM / 16 / 4; ++it) {   // 256 iters x 4 edges
        const unsigned ed  = edges_w[ebase + it * 4 + eg];
        const unsigned dst = ed & 0xFFFFu;
        const unsigned src = ed >> 16;
        const unsigned a = probs_w[dst * CSW + ch];
        const unsigned b = probs_w[src * CSW + ch];
        cons = __dp4a(__vsubus4(a, b), 0x01010101u, cons);
    }

    // ---- CTA reduction ----
#pragma unroll
    for (int o = 16; o; o >>= 1) {
        bce_acc += __shfl_xor_sync(0xffffffffu, bce_acc, o);
        cons    += __shfl_xor_sync(0xffffffffu, cons, o);
    }
    if (lane == 0) { s_red_b[warp] = (double)bce_acc; s_red_c[warp] = (double)cons; }
    __syncthreads();

    if (tid == 0) {
        double tb_ = 0.0, tc_ = 0.0;
#pragma unroll
        for (int w = 0; w < 16; ++w) { tb_ += s_red_b[w]; tc_ += s_red_c[w]; }
        g_part_bce[blockIdx.x]  = tb_;
        g_part_cons[blockIdx.x] = (unsigned long long)(long long)tc_;
        __threadfence();
        const unsigned old = atomicAdd(&g_done, 1u);
        s_last = (((old + 1u) & (NUM_CTAS - 1u)) == 0u) ? 1u : 0u;
    }
    __syncthreads();

    // ---- Last CTA finalizes ----
    if (s_last) {
        __threadfence();
        double vb = 0.0, vc = 0.0;
        if (tid < NUM_CTAS) {
            vb = __ldcg(&g_part_bce[tid]);
            vc = (double)__ldcg(&g_part_cons[tid]);
        }
#pragma unroll
        for (int o = 16; o; o >>= 1) {
            vb += __shfl_xor_sync(0xffffffffu, vb, o);
            vc += __shfl_xor_sync(0xffffffffu, vc, o);
        }
        if (lane == 0) { s_red_b[warp] = vb; s_red_c[warp] = vc; }
        __syncthreads();
        if (tid == 0) {
            double B_ = 0.0, C_ = 0.0;
#pragma unroll
            for (int w = 0; w < 16; ++w) { B_ += s_red_b[w]; C_ += s_red_c[w]; }
            const double denom = (double)B_DIM * (double)N_DIM;
            out[0] = (float)((B_ + 0.5 * (C_ / 255.0)) / denom);
        }
    }
}

extern "C" void kernel_launch(void* const* d_in, const int* in_sizes, int n_in,
                              void* d_out, int out_size) {
    (void)in_sizes; (void)n_in; (void)out_size;
    static bool attr_set = false;
    if (!attr_set) {
        cudaFuncSetAttribute(hl_fused_kernel,
                             cudaFuncAttributeMaxDynamicSharedMemorySize, SMEM_BYTES);
        attr_set = true;
    }
    hl_fused_kernel<<<NUM_CTAS, THREADS, SMEM_BYTES>>>(
        (const float*)d_in[0], (const float*)d_in[1], (const float*)d_in[2],
        (const int*)d_in[3], (const int*)d_in[4], (float*)d_out);
}

// round 8
// speedup vs baseline: 1.7681x; 1.7681x over previous
#include <cuda_runtime.h>
#include <cstdint>

// HierarchicalLoss on GB300 sm_103a — occupancy-optimized fused kernel.
//
// loss = mean(level_w[n] * (softplus(x) - x*t))
//      + 0.5/(B*N) * sum_{b,e} relu(sigmoid(x[b,dst_e]) - sigmoid(x[b,src_e]))
//
// R5 profile: occ 24.9%, issue 33.8%, DRAM 17.5% -> latency-bound at 16 warps/SM.
// Fix: 512 CTAs x 8 rows x 256 threads, 48KB smem/CTA -> 4 CTAs/SM, 32 warps/SM.
// Phase 1: stream outputs/targets (float4), weighted BCE via exp/log MUFU,
//          quantize sigmoid to u8, row-packed probs[col][row] in smem
//          (col stride 12B = 2 data words + 1 pad).
// Phase 2: 16 edges x 2 chunks per warp-iter; edges read from gmem (L2-hot);
//          __vsubus4 (per-byte relu) + __dp4a exact integer accumulation.
// Finalize: per-CTA partial slots (overwritten -> graph-replay safe);
//          last CTA via monotonic counter reduces 512 partials.

#define B_DIM 4096
#define N_DIM 4096
#define E_DIM 16384
#define ROWS_PER_CTA 8
#define NUM_CTAS (B_DIM / ROWS_PER_CTA)      // 512
#define THREADS 256
#define NWARPS (THREADS / 32)                 // 8
#define CSW 3                                 // 12 B column stride (8 rows + 4B pad)
#define PROBS_BYTES (N_DIM * CSW * 4)         // 49152
#define SMEM_BYTES PROBS_BYTES

__device__ double             g_part_bce[NUM_CTAS];
__device__ unsigned long long g_part_cons[NUM_CTAS];
__device__ unsigned int       g_done;   // monotonic; 2^32 is a multiple of 512

__global__ __launch_bounds__(THREADS, 4)
void hl_fused_kernel(const float* __restrict__ outputs,
                     const float* __restrict__ targets,
                     const float* __restrict__ level_w,
                     const int* __restrict__ edge_src,
                     const int* __restrict__ edge_dst,
                     float* __restrict__ out) {
    extern __shared__ unsigned char smem[];
    unsigned* probs_w = reinterpret_cast<unsigned*>(smem);
    __shared__ double   s_red_b[NWARPS];
    __shared__ double   s_red_c[NWARPS];
    __shared__ unsigned s_last;

    const int tid = threadIdx.x;

    // ---- Phase 1: BCE + quantized sigmoid into smem ----
    // g selects 4-row group (2 groups cover 8 rows), cb selects float4 column block.
    const int g  = tid & 1;
    const int cb = tid >> 1;                   // 0..127
    const int rbase = blockIdx.x * ROWS_PER_CTA + 4 * g;
    const size_t cbase = (size_t)rbase * N_DIM + 4 * cb;
    const int ccol = 4 * cb;

    float bce_acc = 0.f;

#pragma unroll 1
    for (int i = 0; i < 8; ++i) {
        const int c0 = ccol + 512 * i;
        const size_t b0 = cbase + 512 * i;

        float4 X[4], T[4];
#pragma unroll
        for (int rr = 0; rr < 4; ++rr) {
            X[rr] = *reinterpret_cast<const float4*>(outputs + b0 + (size_t)rr * N_DIM);
            T[rr] = *reinterpret_cast<const float4*>(targets + b0 + (size_t)rr * N_DIM);
        }
        const float4 w4 = *reinterpret_cast<const float4*>(level_w + c0);

        unsigned pk0 = 0, pk1 = 0, pk2 = 0, pk3 = 0;
#pragma unroll
        for (int rr = 0; rr < 4; ++rr) {
            {   float e = __expf(-X[rr].x); float u = 1.f + e; float lp = __logf(u);
                bce_acc = fmaf(w4.x, fmaf(X[rr].x, 1.f - T[rr].x, lp), bce_acc);
                pk0 |= __float2uint_rn(__fdividef(255.f, u)) << (8 * rr); }
            {   float e = __expf(-X[rr].y); float u = 1.f + e; float lp = __logf(u);
                bce_acc = fmaf(w4.y, fmaf(X[rr].y, 1.f - T[rr].y, lp), bce_acc);
                pk1 |= __float2uint_rn(__fdividef(255.f, u)) << (8 * rr); }
            {   float e = __expf(-X[rr].z); float u = 1.f + e; float lp = __logf(u);
                bce_acc = fmaf(w4.z, fmaf(X[rr].z, 1.f - T[rr].z, lp), bce_acc);
                pk2 |= __float2uint_rn(__fdividef(255.f, u)) << (8 * rr); }
            {   float e = __expf(-X[rr].w); float u = 1.f + e; float lp = __logf(u);
                bce_acc = fmaf(w4.w, fmaf(X[rr].w, 1.f - T[rr].w, lp), bce_acc);
                pk3 |= __float2uint_rn(__fdividef(255.f, u)) << (8 * rr); }
        }
        // word index (c0+j)*3 + g
        const int wb = c0 * CSW + g;
        probs_w[wb]           = pk0;
        probs_w[wb + CSW]     = pk1;
        probs_w[wb + 2 * CSW] = pk2;
        probs_w[wb + 3 * CSW] = pk3;
    }

    __syncthreads();

    // ---- Phase 2: edge consistency (SIMD u8), edges streamed from gmem/L2 ----
    const int warp = tid >> 5;
    const int lane = tid & 31;
    const int eg = lane >> 1;   // 16 edges per warp-iter
    const int ch = lane & 1;    // 2 four-row chunks

    unsigned cons = 0;
    const int ebase = warp * (E_DIM / NWARPS) + eg;   // 2048 edges per warp

#pragma unroll 4
    for (int it = 0; it < E_DIM / NWARPS / 16; ++it) {   // 128 iters x 16 edges
        const int idx = ebase + it * 16;
        const unsigned dst = (unsigned)__ldg(edge_dst + idx);
        const unsigned src = (unsigned)__ldg(edge_src + idx);
        const unsigned a = probs_w[dst * CSW + ch];
        const unsigned b = probs_w[src * CSW + ch];
        cons = __dp4a(__vsubus4(a, b), 0x01010101u, cons);
    }

    // ---- CTA reduction ----
#pragma unroll
    for (int o = 16; o; o >>= 1) {
        bce_acc += __shfl_xor_sync(0xffffffffu, bce_acc, o);
        cons    += __shfl_xor_sync(0xffffffffu, cons, o);
    }
    if (lane == 0) { s_red_b[warp] = (double)bce_acc; s_red_c[warp] = (double)cons; }
    __syncthreads();

    if (tid == 0) {
        double tb_ = 0.0, tc_ = 0.0;
#pragma unroll
        for (int w = 0; w < NWARPS; ++w) { tb_ += s_red_b[w]; tc_ += s_red_c[w]; }
        g_part_bce[blockIdx.x]  = tb_;
        g_part_cons[blockIdx.x] = (unsigned long long)(long long)tc_;
        __threadfence();
        const unsigned old = atomicAdd(&g_done, 1u);
        s_last = (((old + 1u) & (NUM_CTAS - 1u)) == 0u) ? 1u : 0u;
    }
    __syncthreads();

    // ---- Last CTA finalizes (512 partials, 256 threads -> 2 each) ----
    if (s_last) {
        __threadfence();
        double vb = __ldcg(&g_part_bce[tid])  + __ldcg(&g_part_bce[tid + THREADS]);
        double vc = (double)__ldcg(&g_part_cons[tid])
                  + (double)__ldcg(&g_part_cons[tid + THREADS]);
#pragma unroll
        for (int o = 16; o; o >>= 1) {
            vb += __shfl_xor_sync(0xffffffffu, vb, o);
            vc += __shfl_xor_sync(0xffffffffu, vc, o);
        }
        if (lane == 0) { s_red_b[warp] = vb; s_red_c[warp] = vc; }
        __syncthreads();
        if (tid == 0) {
            double B_ = 0.0, C_ = 0.0;
#pragma unroll
            for (int w = 0; w < NWARPS; ++w) { B_ += s_red_b[w]; C_ += s_red_c[w]; }
            const double denom = (double)B_DIM * (double)N_DIM;
            out[0] = (float)((B_ + 0.5 * (C_ / 255.0)) / denom);
        }
    }
}

extern "C" void kernel_launch(void* const* d_in, const int* in_sizes, int n_in,
                              void* d_out, int out_size) {
    (void)in_sizes; (void)n_in; (void)out_size;
    static bool attr_set = false;
    if (!attr_set) {
        cudaFuncSetAttribute(hl_fused_kernel,
                             cudaFuncAttributeMaxDynamicSharedMemorySize, SMEM_BYTES);
        attr_set = true;
    }
    hl_fused_kernel<<<NUM_CTAS, THREADS, SMEM_BYTES>>>(
        (const float*)d_in[0], (const float*)d_in[1], (const float*)d_in[2],
        (const int*)d_in[3], (const int*)d_in[4], (float*)d_out);
}